// round 3
// baseline (speedup 1.0000x reference)
#include <cuda_runtime.h>
#include <cuda_bf16.h>
#include <cstddef>

#define NMAX   50000
#define EMAX   800000
#define IN_DIM 256
#define HID    128
#define ZDIM   64
#define LN_EPS 1e-5f

// ---------------- device scratch (static, no allocation) ----------------
__device__ float g_h0[(size_t)NMAX * IN_DIM];   // LayerNorm output
__device__ float g_t [(size_t)NMAX * HID];      // GEMM output (X @ W), reused
__device__ float g_h [(size_t)NMAX * HID];      // layer output after agg+relu
__device__ float g_dinv[NMAX];
__device__ float g_w  [EMAX];                   // per-edge coef dinv[s]*dinv[d]
__device__ int   g_deg[NMAX];
__device__ int   g_rowptr[NMAX + 1];
__device__ int   g_cursor[NMAX];
__device__ int   g_cidx[EMAX];                  // src indices sorted by dst

__device__ __forceinline__ int clampi(int v, int lo, int hi) {
    return min(max(v, lo), hi);
}

// ---------------- LayerNorm: one warp per 256-wide row ----------------
__global__ void ln_kernel(const float* __restrict__ x,
                          const float* __restrict__ gamma,
                          const float* __restrict__ beta, int n) {
    int row  = blockIdx.x * 8 + (threadIdx.x >> 5);
    if (row >= n) return;
    int lane = threadIdx.x & 31;
    const float* xr = x + (size_t)row * IN_DIM;

    float4 v0 = *(const float4*)(xr + lane * 8);
    float4 v1 = *(const float4*)(xr + lane * 8 + 4);

    float s  = v0.x + v0.y + v0.z + v0.w + v1.x + v1.y + v1.z + v1.w;
    float sq = v0.x*v0.x + v0.y*v0.y + v0.z*v0.z + v0.w*v0.w
             + v1.x*v1.x + v1.y*v1.y + v1.z*v1.z + v1.w*v1.w;
    #pragma unroll
    for (int off = 16; off > 0; off >>= 1) {
        s  += __shfl_xor_sync(0xffffffffu, s,  off);
        sq += __shfl_xor_sync(0xffffffffu, sq, off);
    }
    float mu  = s * (1.0f / IN_DIM);
    float var = sq * (1.0f / IN_DIM) - mu * mu;
    float rs  = rsqrtf(var + LN_EPS);

    float4 g0 = *(const float4*)(gamma + lane * 8);
    float4 g1 = *(const float4*)(gamma + lane * 8 + 4);
    float4 be0 = *(const float4*)(beta + lane * 8);
    float4 be1 = *(const float4*)(beta + lane * 8 + 4);

    float4 o0, o1;
    o0.x = (v0.x - mu) * rs * g0.x + be0.x;
    o0.y = (v0.y - mu) * rs * g0.y + be0.y;
    o0.z = (v0.z - mu) * rs * g0.z + be0.z;
    o0.w = (v0.w - mu) * rs * g0.w + be0.w;
    o1.x = (v1.x - mu) * rs * g1.x + be1.x;
    o1.y = (v1.y - mu) * rs * g1.y + be1.y;
    o1.z = (v1.z - mu) * rs * g1.z + be1.z;
    o1.w = (v1.w - mu) * rs * g1.w + be1.w;

    float* outr = g_h0 + (size_t)row * IN_DIM;
    *(float4*)(outr + lane * 8)     = o0;
    *(float4*)(outr + lane * 8 + 4) = o1;
}

// ---------------- degree / CSR build ----------------
__global__ void zero_deg_kernel(int n) {
    int i = blockIdx.x * blockDim.x + threadIdx.x;
    if (i < n) g_deg[i] = 0;
}

__global__ void count_kernel(const int* __restrict__ ei, int e, int n) {
    int i = blockIdx.x * blockDim.x + threadIdx.x;
    if (i >= e) return;
    int d = clampi(ei[e + i], 0, n - 1);
    atomicAdd(&g_deg[d], 1);
}

__global__ void dinv_kernel(int n) {
    int i = blockIdx.x * blockDim.x + threadIdx.x;
    if (i < n) g_dinv[i] = rsqrtf(1.0f + (float)g_deg[i]);
}

// single-block exclusive scan of g_deg -> g_rowptr (and g_cursor)
__global__ void scan_kernel(int n) {
    __shared__ int warp_sums[32];
    __shared__ int s_carry;
    int t = threadIdx.x, lane = t & 31, wid = t >> 5;
    if (t == 0) s_carry = 0;
    __syncthreads();
    for (int base = 0; base < n; base += 1024) {
        int i = base + t;
        int v = (i < n) ? g_deg[i] : 0;
        int x = v;
        #pragma unroll
        for (int off = 1; off < 32; off <<= 1) {
            int y = __shfl_up_sync(0xffffffffu, x, off);
            if (lane >= off) x += y;
        }
        if (lane == 31) warp_sums[wid] = x;
        __syncthreads();
        if (wid == 0) {
            int ws = warp_sums[lane];
            #pragma unroll
            for (int off = 1; off < 32; off <<= 1) {
                int y = __shfl_up_sync(0xffffffffu, ws, off);
                if (lane >= off) ws += y;
            }
            warp_sums[lane] = ws;
        }
        __syncthreads();
        int warp_off = (wid == 0) ? 0 : warp_sums[wid - 1];
        int excl = s_carry + warp_off + x - v;
        if (i < n) { g_rowptr[i] = excl; g_cursor[i] = excl; }
        int total = warp_sums[31];
        __syncthreads();
        if (t == 0) s_carry += total;
        __syncthreads();
    }
    if (t == 0) g_rowptr[n] = s_carry;
}

__global__ void scatter_kernel(const int* __restrict__ ei, int e, int n) {
    int i = blockIdx.x * blockDim.x + threadIdx.x;
    if (i >= e) return;
    int s = clampi(ei[i],     0, n - 1);
    int d = clampi(ei[e + i], 0, n - 1);
    int pos = atomicAdd(&g_cursor[d], 1);
    g_cidx[pos] = s;
    g_w[pos] = g_dinv[s] * g_dinv[d];
}

// ---------------- fp32 SGEMM: g_t[M,NOUT] = A[M,K] @ W[K,NOUT] ----------------
// ASEL: 0 -> A = g_h0, 1 -> A = g_h  (device globals referenced directly)
template <int K, int NOUT, int ASEL>
__launch_bounds__(256)
__global__ void gemm_kernel(const float* __restrict__ W, int M) {
    const float* __restrict__ A = (ASEL == 0) ? g_h0 : g_h;
    float* __restrict__ C = g_t;

    constexpr int BM = 64, BK = 32;
    constexpr int TN = NOUT / 16;          // 8 (NOUT=128) or 4 (NOUT=64)
    __shared__ float As[BK][BM];
    __shared__ float Bs[BK][NOUT];

    int tid = threadIdx.x;
    int m0  = blockIdx.x * BM;
    int ty  = tid >> 4, tx = tid & 15;

    float acc[4][TN];
    #pragma unroll
    for (int i = 0; i < 4; i++)
        #pragma unroll
        for (int j = 0; j < TN; j++) acc[i][j] = 0.0f;

    for (int kt = 0; kt < K; kt += BK) {
        // A tile: 64 rows x 32 k, transposed into smem
        #pragma unroll
        for (int p = 0; p < 2; p++) {
            int r  = (tid >> 3) + p * 32;
            int kc = (tid & 7) * 4;
            int gr = m0 + r;
            float4 a = make_float4(0.f, 0.f, 0.f, 0.f);
            if (gr < M) a = *(const float4*)(A + (size_t)gr * K + kt + kc);
            As[kc + 0][r] = a.x;
            As[kc + 1][r] = a.y;
            As[kc + 2][r] = a.z;
            As[kc + 3][r] = a.w;
        }
        // B tile: 32 x NOUT
        constexpr int CPR = NOUT / 4;       // float4 loads per row
        constexpr int RPP = 256 / CPR;      // rows per pass
        #pragma unroll
        for (int p = 0; p < BK / RPP; p++) {
            int r = (tid / CPR) + p * RPP;
            int c = (tid % CPR) * 4;
            *(float4*)(&Bs[r][c]) = *(const float4*)(W + (size_t)(kt + r) * NOUT + c);
        }
        __syncthreads();
        #pragma unroll
        for (int kk = 0; kk < BK; kk++) {
            float4 a = *(float4*)(&As[kk][ty * 4]);
            float bv[TN];
            #pragma unroll
            for (int j = 0; j < TN; j++) bv[j] = Bs[kk][tx * TN + j];
            #pragma unroll
            for (int j = 0; j < TN; j++) {
                acc[0][j] += a.x * bv[j];
                acc[1][j] += a.y * bv[j];
                acc[2][j] += a.z * bv[j];
                acc[3][j] += a.w * bv[j];
            }
        }
        __syncthreads();
    }
    #pragma unroll
    for (int i = 0; i < 4; i++) {
        int row = m0 + ty * 4 + i;
        if (row < M) {
            #pragma unroll
            for (int j = 0; j < TN; j += 4) {
                float4 o = make_float4(acc[i][j], acc[i][j+1], acc[i][j+2], acc[i][j+3]);
                *(float4*)(C + (size_t)row * NOUT + tx * TN + j) = o;
            }
        }
    }
}

// ---------------- aggregation: out[v] = sum_{(s->v)} t[s]*w + t[v]*dinv[v]^2 + b ----------------
// Reads g_t. TO_TMP: true -> writes g_h; false -> writes out pointer arg.
template <int D, bool RELU, bool TO_TMP>
__global__ void agg_kernel(const float* __restrict__ bias,
                           float* __restrict__ outp, int n) {
    const float* __restrict__ t = g_t;
    constexpr int GS  = D / 4;        // lanes per row (32 for D=128, 16 for D=64)
    constexpr int GPB = 128 / GS;
    int g = blockIdx.x * GPB + threadIdx.x / GS;
    if (g >= n) return;
    int lane = threadIdx.x % GS;
    int c = lane * 4;

    float dv = g_dinv[g];
    float sc = dv * dv;
    float4 b4 = *(const float4*)(bias + c);
    float4 tv = *(const float4*)(t + (size_t)g * D + c);
    float4 acc;
    acc.x = tv.x * sc + b4.x;
    acc.y = tv.y * sc + b4.y;
    acc.z = tv.z * sc + b4.z;
    acc.w = tv.w * sc + b4.w;

    int e0 = g_rowptr[g], e1 = g_rowptr[g + 1];
    for (int e = e0; e < e1; e++) {
        int s   = g_cidx[e];
        float w = g_w[e];
        float4 h = *(const float4*)(t + (size_t)s * D + c);
        acc.x += h.x * w;
        acc.y += h.y * w;
        acc.z += h.z * w;
        acc.w += h.w * w;
    }
    if (RELU) {
        acc.x = fmaxf(acc.x, 0.f);
        acc.y = fmaxf(acc.y, 0.f);
        acc.z = fmaxf(acc.z, 0.f);
        acc.w = fmaxf(acc.w, 0.f);
    }
    float* o = TO_TMP ? (g_h + (size_t)g * D + c) : (outp + (size_t)g * D + c);
    *(float4*)o = acc;
}

// ---------------- launch ----------------
extern "C" void kernel_launch(void* const* d_in, const int* in_sizes, int n_in,
                              void* d_out, int out_size) {
    const float* x     = (const float*)d_in[0];
    const int*   ei    = (const int*)d_in[1];     // int32: JAX x64 disabled
    const float* gamma = (const float*)d_in[2];
    const float* beta  = (const float*)d_in[3];
    const float* W1    = (const float*)d_in[4];
    const float* b1    = (const float*)d_in[5];
    const float* W2    = (const float*)d_in[6];
    const float* b2    = (const float*)d_in[7];
    const float* W3    = (const float*)d_in[8];
    const float* b3    = (const float*)d_in[9];
    float* out = (float*)d_out;

    int n = in_sizes[0] / IN_DIM;   // 50000
    int e = in_sizes[1] / 2;        // 800000

    // LayerNorm
    ln_kernel<<<(n + 7) / 8, 256>>>(x, gamma, beta, n);

    // degree + CSR build
    zero_deg_kernel<<<(n + 255) / 256, 256>>>(n);
    count_kernel<<<(e + 255) / 256, 256>>>(ei, e, n);
    dinv_kernel<<<(n + 255) / 256, 256>>>(n);
    scan_kernel<<<1, 1024>>>(n);
    scatter_kernel<<<(e + 255) / 256, 256>>>(ei, e, n);

    // layer 1: 256 -> 128, relu
    gemm_kernel<IN_DIM, HID, 0><<<(n + 63) / 64, 256>>>(W1, n);
    agg_kernel<HID, true, true><<<(n + 3) / 4, 128>>>(b1, nullptr, n);

    // layer 2: 128 -> 128, relu
    gemm_kernel<HID, HID, 1><<<(n + 63) / 64, 256>>>(W2, n);
    agg_kernel<HID, true, true><<<(n + 3) / 4, 128>>>(b2, nullptr, n);

    // layer 3: 128 -> 64, no relu, writes d_out
    gemm_kernel<HID, ZDIM, 1><<<(n + 63) / 64, 256>>>(W3, n);
    agg_kernel<ZDIM, false, false><<<(n + 7) / 8, 128>>>(b3, out, n);
}

// round 4
// speedup vs baseline: 1.6517x; 1.6517x over previous
#include <cuda_runtime.h>
#include <cuda_bf16.h>
#include <cstddef>

#define NMAX   50000
#define EMAX   800000
#define IN_DIM 256
#define HID    128
#define ZDIM   64
#define LN_EPS 1e-5f

// ---------------- device scratch (static, no allocation) ----------------
__device__ float g_h0[(size_t)NMAX * IN_DIM];   // LayerNorm output
__device__ float g_t [(size_t)NMAX * HID];      // GEMM output (X @ W), reused
__device__ float g_h [(size_t)NMAX * HID];      // layer output after agg+relu
__device__ float g_dinv[NMAX];
__device__ float g_w  [EMAX];                   // per-edge coef dinv[s]*dinv[d]
__device__ int   g_deg[NMAX];
__device__ int   g_rowptr[NMAX + 1];
__device__ int   g_cursor[NMAX];
__device__ int   g_cidx[EMAX];                  // src indices sorted by dst

__device__ __forceinline__ int clampi(int v, int lo, int hi) {
    return min(max(v, lo), hi);
}

__device__ __forceinline__ float to_tf32(float x) {
    unsigned u;
    asm("cvt.rna.tf32.f32 %0, %1;" : "=r"(u) : "f"(x));
    return __uint_as_float(u);
}

// ---------------- LayerNorm: one warp per 256-wide row ----------------
__global__ void ln_kernel(const float* __restrict__ x,
                          const float* __restrict__ gamma,
                          const float* __restrict__ beta, int n) {
    int row  = blockIdx.x * 8 + (threadIdx.x >> 5);
    if (row >= n) return;
    int lane = threadIdx.x & 31;
    const float* xr = x + (size_t)row * IN_DIM;

    float4 v0 = *(const float4*)(xr + lane * 8);
    float4 v1 = *(const float4*)(xr + lane * 8 + 4);

    float s  = v0.x + v0.y + v0.z + v0.w + v1.x + v1.y + v1.z + v1.w;
    float sq = v0.x*v0.x + v0.y*v0.y + v0.z*v0.z + v0.w*v0.w
             + v1.x*v1.x + v1.y*v1.y + v1.z*v1.z + v1.w*v1.w;
    #pragma unroll
    for (int off = 16; off > 0; off >>= 1) {
        s  += __shfl_xor_sync(0xffffffffu, s,  off);
        sq += __shfl_xor_sync(0xffffffffu, sq, off);
    }
    float mu  = s * (1.0f / IN_DIM);
    float var = sq * (1.0f / IN_DIM) - mu * mu;
    float rs  = rsqrtf(var + LN_EPS);

    float4 g0 = *(const float4*)(gamma + lane * 8);
    float4 g1 = *(const float4*)(gamma + lane * 8 + 4);
    float4 be0 = *(const float4*)(beta + lane * 8);
    float4 be1 = *(const float4*)(beta + lane * 8 + 4);

    float4 o0, o1;
    o0.x = (v0.x - mu) * rs * g0.x + be0.x;
    o0.y = (v0.y - mu) * rs * g0.y + be0.y;
    o0.z = (v0.z - mu) * rs * g0.z + be0.z;
    o0.w = (v0.w - mu) * rs * g0.w + be0.w;
    o1.x = (v1.x - mu) * rs * g1.x + be1.x;
    o1.y = (v1.y - mu) * rs * g1.y + be1.y;
    o1.z = (v1.z - mu) * rs * g1.z + be1.z;
    o1.w = (v1.w - mu) * rs * g1.w + be1.w;

    float* outr = g_h0 + (size_t)row * IN_DIM;
    *(float4*)(outr + lane * 8)     = o0;
    *(float4*)(outr + lane * 8 + 4) = o1;
}

// ---------------- degree / CSR build ----------------
__global__ void zero_deg_kernel(int n) {
    int i = blockIdx.x * blockDim.x + threadIdx.x;
    if (i < n) g_deg[i] = 0;
}

__global__ void count_kernel(const int* __restrict__ ei, int e, int n) {
    int i = blockIdx.x * blockDim.x + threadIdx.x;
    if (i >= e) return;
    int d = clampi(ei[e + i], 0, n - 1);
    atomicAdd(&g_deg[d], 1);
}

__global__ void dinv_kernel(int n) {
    int i = blockIdx.x * blockDim.x + threadIdx.x;
    if (i < n) g_dinv[i] = rsqrtf(1.0f + (float)g_deg[i]);
}

// single-block exclusive scan of g_deg -> g_rowptr (and g_cursor)
__global__ void scan_kernel(int n) {
    __shared__ int warp_sums[32];
    __shared__ int s_carry;
    int t = threadIdx.x, lane = t & 31, wid = t >> 5;
    if (t == 0) s_carry = 0;
    __syncthreads();
    for (int base = 0; base < n; base += 1024) {
        int i = base + t;
        int v = (i < n) ? g_deg[i] : 0;
        int x = v;
        #pragma unroll
        for (int off = 1; off < 32; off <<= 1) {
            int y = __shfl_up_sync(0xffffffffu, x, off);
            if (lane >= off) x += y;
        }
        if (lane == 31) warp_sums[wid] = x;
        __syncthreads();
        if (wid == 0) {
            int ws = warp_sums[lane];
            #pragma unroll
            for (int off = 1; off < 32; off <<= 1) {
                int y = __shfl_up_sync(0xffffffffu, ws, off);
                if (lane >= off) ws += y;
            }
            warp_sums[lane] = ws;
        }
        __syncthreads();
        int warp_off = (wid == 0) ? 0 : warp_sums[wid - 1];
        int excl = s_carry + warp_off + x - v;
        if (i < n) { g_rowptr[i] = excl; g_cursor[i] = excl; }
        int total = warp_sums[31];
        __syncthreads();
        if (t == 0) s_carry += total;
        __syncthreads();
    }
    if (t == 0) g_rowptr[n] = s_carry;
}

__global__ void scatter_kernel(const int* __restrict__ ei, int e, int n) {
    int i = blockIdx.x * blockDim.x + threadIdx.x;
    if (i >= e) return;
    int s = clampi(ei[i],     0, n - 1);
    int d = clampi(ei[e + i], 0, n - 1);
    int pos = atomicAdd(&g_cursor[d], 1);
    g_cidx[pos] = s;
    g_w[pos] = g_dinv[s] * g_dinv[d];
}

// ---------------- tf32 tensor-core GEMM: g_t[M,NOUT] = A[M,K] @ W[K,NOUT] ----
// mma.sync.m16n8k8 tf32. BM=128, BK=32, 8 warps in 4x2 (32 rows x NOUT/2 cols).
// ASEL: 0 -> A = g_h0, 1 -> A = g_h
template <int K, int NOUT, int ASEL>
__launch_bounds__(256)
__global__ void gemm_tc_kernel(const float* __restrict__ W, int M) {
    const float* __restrict__ A = (ASEL == 0) ? g_h0 : g_h;
    float* __restrict__ C = g_t;

    constexpr int BM = 128, BK = 32;
    constexpr int NPW = NOUT / 2;     // cols per warp (64 or 32)
    constexpr int NT  = NPW / 8;      // n8 tiles per warp (8 or 4)

    __shared__ float As[BK][BM + 8];
    __shared__ float Bs[BK][NOUT + 8];

    int tid  = threadIdx.x;
    int wid  = tid >> 5;
    int lane = tid & 31;
    int qr   = lane >> 2;     // group id 0..7
    int qc   = lane & 3;      // thread-in-group 0..3
    int wr   = wid >> 1;      // 0..3 : row strip (32 rows)
    int wc   = wid & 1;       // 0..1 : col half
    int m0   = blockIdx.x * BM;

    float c[2][NT][4];
    #pragma unroll
    for (int mi = 0; mi < 2; mi++)
        #pragma unroll
        for (int ni = 0; ni < NT; ni++)
            #pragma unroll
            for (int j = 0; j < 4; j++) c[mi][ni][j] = 0.0f;

    for (int kt = 0; kt < K; kt += BK) {
        // A tile: 128 rows x 32 k, transposed into As[k][m], tf32-rounded
        #pragma unroll
        for (int p = 0; p < 4; p++) {
            int r  = (tid >> 3) + p * 32;
            int kc = (tid & 7) * 4;
            int gr = m0 + r;
            float4 a = make_float4(0.f, 0.f, 0.f, 0.f);
            if (gr < M) a = *(const float4*)(A + (size_t)gr * K + kt + kc);
            As[kc + 0][r] = to_tf32(a.x);
            As[kc + 1][r] = to_tf32(a.y);
            As[kc + 2][r] = to_tf32(a.z);
            As[kc + 3][r] = to_tf32(a.w);
        }
        // B tile: 32 x NOUT, tf32-rounded
        constexpr int CPR = NOUT / 4;       // float4 loads per row
        constexpr int RPP = 256 / CPR;      // rows per pass
        #pragma unroll
        for (int p = 0; p < BK / RPP; p++) {
            int r = (tid / CPR) + p * RPP;
            int cc = (tid % CPR) * 4;
            float4 b = *(const float4*)(W + (size_t)(kt + r) * NOUT + cc);
            Bs[r][cc + 0] = to_tf32(b.x);
            Bs[r][cc + 1] = to_tf32(b.y);
            Bs[r][cc + 2] = to_tf32(b.z);
            Bs[r][cc + 3] = to_tf32(b.w);
        }
        __syncthreads();

        #pragma unroll
        for (int ks = 0; ks < BK / 8; ks++) {
            int k0 = ks * 8;
            // A fragments for the two m16 strips
            unsigned af[2][4];
            #pragma unroll
            for (int mi = 0; mi < 2; mi++) {
                int rb = wr * 32 + mi * 16;
                af[mi][0] = __float_as_uint(As[k0 + qc    ][rb + qr    ]);
                af[mi][1] = __float_as_uint(As[k0 + qc    ][rb + qr + 8]);
                af[mi][2] = __float_as_uint(As[k0 + qc + 4][rb + qr    ]);
                af[mi][3] = __float_as_uint(As[k0 + qc + 4][rb + qr + 8]);
            }
            #pragma unroll
            for (int ni = 0; ni < NT; ni++) {
                int col = wc * NPW + ni * 8 + qr;
                unsigned b0 = __float_as_uint(Bs[k0 + qc    ][col]);
                unsigned b1 = __float_as_uint(Bs[k0 + qc + 4][col]);
                #pragma unroll
                for (int mi = 0; mi < 2; mi++) {
                    asm volatile(
                        "mma.sync.aligned.m16n8k8.row.col.f32.tf32.tf32.f32 "
                        "{%0,%1,%2,%3}, {%4,%5,%6,%7}, {%8,%9}, {%0,%1,%2,%3};"
                        : "+f"(c[mi][ni][0]), "+f"(c[mi][ni][1]),
                          "+f"(c[mi][ni][2]), "+f"(c[mi][ni][3])
                        : "r"(af[mi][0]), "r"(af[mi][1]),
                          "r"(af[mi][2]), "r"(af[mi][3]),
                          "r"(b0), "r"(b1));
                }
            }
        }
        __syncthreads();
    }

    // epilogue: c0,c1 -> (row, col..col+1), c2,c3 -> (row+8, col..col+1)
    #pragma unroll
    for (int mi = 0; mi < 2; mi++) {
        int row = m0 + wr * 32 + mi * 16 + qr;
        #pragma unroll
        for (int ni = 0; ni < NT; ni++) {
            int col = wc * NPW + ni * 8 + 2 * qc;
            if (row < M) {
                float2 v0 = make_float2(c[mi][ni][0], c[mi][ni][1]);
                *(float2*)(C + (size_t)row * NOUT + col) = v0;
            }
            if (row + 8 < M) {
                float2 v1 = make_float2(c[mi][ni][2], c[mi][ni][3]);
                *(float2*)(C + (size_t)(row + 8) * NOUT + col) = v1;
            }
        }
    }
}

// ---------------- aggregation: out[v] = sum_{(s->v)} t[s]*w + t[v]*dinv[v]^2 + b ----------------
// Reads g_t. TO_TMP: true -> writes g_h; false -> writes out pointer arg.
template <int D, bool RELU, bool TO_TMP>
__global__ void agg_kernel(const float* __restrict__ bias,
                           float* __restrict__ outp, int n) {
    const float* __restrict__ t = g_t;
    constexpr int GS  = D / 4;        // lanes per row (32 for D=128, 16 for D=64)
    constexpr int GPB = 128 / GS;
    int g = blockIdx.x * GPB + threadIdx.x / GS;
    if (g >= n) return;
    int lane = threadIdx.x % GS;
    int c = lane * 4;

    float dv = g_dinv[g];
    float sc = dv * dv;
    float4 b4 = *(const float4*)(bias + c);
    float4 tv = *(const float4*)(t + (size_t)g * D + c);
    float4 acc;
    acc.x = tv.x * sc + b4.x;
    acc.y = tv.y * sc + b4.y;
    acc.z = tv.z * sc + b4.z;
    acc.w = tv.w * sc + b4.w;

    int e0 = g_rowptr[g], e1 = g_rowptr[g + 1];
    for (int e = e0; e < e1; e++) {
        int s   = g_cidx[e];
        float w = g_w[e];
        float4 h = *(const float4*)(t + (size_t)s * D + c);
        acc.x += h.x * w;
        acc.y += h.y * w;
        acc.z += h.z * w;
        acc.w += h.w * w;
    }
    if (RELU) {
        acc.x = fmaxf(acc.x, 0.f);
        acc.y = fmaxf(acc.y, 0.f);
        acc.z = fmaxf(acc.z, 0.f);
        acc.w = fmaxf(acc.w, 0.f);
    }
    float* o = TO_TMP ? (g_h + (size_t)g * D + c) : (outp + (size_t)g * D + c);
    *(float4*)o = acc;
}

// ---------------- launch ----------------
extern "C" void kernel_launch(void* const* d_in, const int* in_sizes, int n_in,
                              void* d_out, int out_size) {
    const float* x     = (const float*)d_in[0];
    const int*   ei    = (const int*)d_in[1];     // int32: JAX x64 disabled
    const float* gamma = (const float*)d_in[2];
    const float* beta  = (const float*)d_in[3];
    const float* W1    = (const float*)d_in[4];
    const float* b1    = (const float*)d_in[5];
    const float* W2    = (const float*)d_in[6];
    const float* b2    = (const float*)d_in[7];
    const float* W3    = (const float*)d_in[8];
    const float* b3    = (const float*)d_in[9];
    float* out = (float*)d_out;

    int n = in_sizes[0] / IN_DIM;   // 50000
    int e = in_sizes[1] / 2;        // 800000

    // LayerNorm
    ln_kernel<<<(n + 7) / 8, 256>>>(x, gamma, beta, n);

    // degree + CSR build
    zero_deg_kernel<<<(n + 255) / 256, 256>>>(n);
    count_kernel<<<(e + 255) / 256, 256>>>(ei, e, n);
    dinv_kernel<<<(n + 255) / 256, 256>>>(n);
    scan_kernel<<<1, 1024>>>(n);
    scatter_kernel<<<(e + 255) / 256, 256>>>(ei, e, n);

    // layer 1: 256 -> 128, relu
    gemm_tc_kernel<IN_DIM, HID, 0><<<(n + 127) / 128, 256>>>(W1, n);
    agg_kernel<HID, true, true><<<(n + 3) / 4, 128>>>(b1, nullptr, n);

    // layer 2: 128 -> 128, relu
    gemm_tc_kernel<HID, HID, 1><<<(n + 127) / 128, 256>>>(W2, n);
    agg_kernel<HID, true, true><<<(n + 3) / 4, 128>>>(b2, nullptr, n);

    // layer 3: 128 -> 64, no relu, writes d_out
    gemm_tc_kernel<HID, ZDIM, 1><<<(n + 127) / 128, 256>>>(W3, n);
    agg_kernel<ZDIM, false, false><<<(n + 7) / 8, 128>>>(b3, out, n);
}